// round 3
// baseline (speedup 1.0000x reference)
#include <cuda_runtime.h>
#include <math.h>

#define NN 50000
#define EE 800000
#define RR 32
#define BB 15
#define HH 8
#define CC 16

// ---- scratch (device globals; no allocation allowed) ----
__device__ int   g_counts[NN * RR];                 // 6.4 MB
__device__ float g_w1[(size_t)RR * NN * HH];        // 51.2 MB
__device__ float g_w2[RR * HH * CC];                // 16 KB
__device__ float g_agg1[NN * HH];                   // 1.6 MB
__device__ float g_x[NN * HH];                      // 1.6 MB
__device__ float g_agg2[NN * CC];                   // 3.2 MB

// ---- 1. zero the accumulators ----
__global__ void k_zero() {
    int i = blockIdx.x * blockDim.x + threadIdx.x;
    int stride = gridDim.x * blockDim.x;
    for (int j = i; j < NN * RR; j += stride) g_counts[j] = 0;
    for (int j = i; j < NN * HH; j += stride) g_agg1[j] = 0.0f;
    for (int j = i; j < NN * CC; j += stride) g_agg2[j] = 0.0f;
}

// ---- 2. per-(target, relation) in-degree counts ----
__global__ void k_count(const int* __restrict__ edge_index,
                        const int* __restrict__ edge_type) {
    int e = blockIdx.x * blockDim.x + threadIdx.x;
    if (e >= EE) return;
    int tgt = __ldg(&edge_index[EE + e]);
    int et  = __ldg(&edge_type[e]);
    atomicAdd(&g_counts[tgt * RR + et], 1);
}

// ---- 3. w1[r,n,h] = sum_b comp1[r,b] * basis1[b,n,h] ----
// parallel over N*H: basis1 read once, writes coalesced per r
__global__ void k_w1(const float* __restrict__ basis1,
                     const float* __restrict__ comp1) {
    __shared__ float sc[RR * BB];
    for (int i = threadIdx.x; i < RR * BB; i += blockDim.x) sc[i] = comp1[i];
    __syncthreads();
    int idx = blockIdx.x * blockDim.x + threadIdx.x;   // over NN*HH
    if (idx >= NN * HH) return;
    float bv[BB];
#pragma unroll
    for (int b = 0; b < BB; b++) bv[b] = __ldg(&basis1[b * (NN * HH) + idx]);
#pragma unroll 4
    for (int r = 0; r < RR; r++) {
        float s = 0.0f;
#pragma unroll
        for (int b = 0; b < BB; b++) s += sc[r * BB + b] * bv[b];
        g_w1[(size_t)r * (NN * HH) + idx] = s;
    }
}

// ---- 4. w2[r,h,c] = sum_b comp2[r,b] * basis2[b,h,c] (tiny) ----
__global__ void k_w2(const float* __restrict__ basis2,
                     const float* __restrict__ comp2) {
    int idx = blockIdx.x * blockDim.x + threadIdx.x;   // over RR*HH*CC = 4096
    if (idx >= RR * HH * CC) return;
    int r  = idx / (HH * CC);
    int hc = idx % (HH * CC);
    float s = 0.0f;
#pragma unroll
    for (int b = 0; b < BB; b++) s += comp2[r * BB + b] * basis2[b * (HH * CC) + hc];
    g_w2[idx] = s;
}

// ---- 5. layer-1 scatter: thread per (edge, h) ----
__global__ void k_scatter1(const int* __restrict__ edge_index,
                           const int* __restrict__ edge_type) {
    long long tid = (long long)blockIdx.x * blockDim.x + threadIdx.x;
    if (tid >= (long long)EE * HH) return;
    int e = (int)(tid >> 3);
    int h = (int)(tid & 7);
    int src = __ldg(&edge_index[e]);
    int tgt = __ldg(&edge_index[EE + e]);
    int et  = __ldg(&edge_type[e]);
    float cnt  = (float)g_counts[tgt * RR + et];
    float norm = 1.0f / fmaxf(cnt, 1.0f);
    float w = g_w1[(size_t)et * (NN * HH) + src * HH + h];
    atomicAdd(&g_agg1[tgt * HH + h], norm * w);
}

// ---- 6a. x = relu(agg1 + root1 + bias1) ----
__global__ void k_relu(const float* __restrict__ root1,
                       const float* __restrict__ bias1) {
    int idx = blockIdx.x * blockDim.x + threadIdx.x;
    if (idx >= NN * HH) return;
    float v = g_agg1[idx] + __ldg(&root1[idx]) + __ldg(&bias1[idx & 7]);
    g_x[idx] = fmaxf(v, 0.0f);
}

// ---- 6b. layer-2 scatter: thread per edge ----
__global__ void k_scatter2(const int* __restrict__ edge_index,
                           const int* __restrict__ edge_type) {
    __shared__ float sw[RR * HH * CC];   // 16 KB
    for (int i = threadIdx.x; i < RR * HH * CC; i += blockDim.x) sw[i] = g_w2[i];
    __syncthreads();
    int e = blockIdx.x * blockDim.x + threadIdx.x;
    if (e >= EE) return;
    int src = __ldg(&edge_index[e]);
    int tgt = __ldg(&edge_index[EE + e]);
    int et  = __ldg(&edge_type[e]);
    float cnt  = (float)g_counts[tgt * RR + et];
    float norm = 1.0f / fmaxf(cnt, 1.0f);
    float4 x0 = *(const float4*)&g_x[src * HH];
    float4 x1 = *(const float4*)&g_x[src * HH + 4];
    float xv[HH] = {x0.x, x0.y, x0.z, x0.w, x1.x, x1.y, x1.z, x1.w};
    const float* w = &sw[et * HH * CC];
#pragma unroll
    for (int c = 0; c < CC; c++) {
        float s = 0.0f;
#pragma unroll
        for (int h = 0; h < HH; h++) s += xv[h] * w[h * CC + c];
        atomicAdd(&g_agg2[tgt * CC + c], norm * s);
    }
}

// ---- 7. out = log_softmax(agg2 + x @ root2 + bias2) ----
__global__ void k_final(const float* __restrict__ root2,
                        const float* __restrict__ bias2,
                        float* __restrict__ out) {
    __shared__ float sr[HH * CC];
    __shared__ float sb[CC];
    for (int i = threadIdx.x; i < HH * CC; i += blockDim.x) sr[i] = root2[i];
    if (threadIdx.x < CC) sb[threadIdx.x] = bias2[threadIdx.x];
    __syncthreads();
    int n = blockIdx.x * blockDim.x + threadIdx.x;
    if (n >= NN) return;
    float4 x0 = *(const float4*)&g_x[n * HH];
    float4 x1 = *(const float4*)&g_x[n * HH + 4];
    float xv[HH] = {x0.x, x0.y, x0.z, x0.w, x1.x, x1.y, x1.z, x1.w};
    float v[CC];
    float m = -INFINITY;
#pragma unroll
    for (int c = 0; c < CC; c++) {
        float s = g_agg2[n * CC + c] + sb[c];
#pragma unroll
        for (int h = 0; h < HH; h++) s += xv[h] * sr[h * CC + c];
        v[c] = s;
        m = fmaxf(m, s);
    }
    float sum = 0.0f;
#pragma unroll
    for (int c = 0; c < CC; c++) sum += __expf(v[c] - m);
    float lse = m + __logf(sum);
#pragma unroll
    for (int c = 0; c < CC; c++) out[n * CC + c] = v[c] - lse;
}

extern "C" void kernel_launch(void* const* d_in, const int* in_sizes, int n_in,
                              void* d_out, int out_size) {
    const int*   edge_index = (const int*)d_in[0];   // (2, E)
    const int*   edge_type  = (const int*)d_in[1];   // (E,)
    const float* basis1     = (const float*)d_in[2]; // (B, N, H)
    const float* comp1      = (const float*)d_in[3]; // (R, B)
    const float* root1      = (const float*)d_in[4]; // (N, H)
    const float* bias1      = (const float*)d_in[5]; // (H,)
    const float* basis2     = (const float*)d_in[6]; // (B, H, C)
    const float* comp2      = (const float*)d_in[7]; // (R, B)
    const float* root2      = (const float*)d_in[8]; // (H, C)
    const float* bias2      = (const float*)d_in[9]; // (C,)
    float* out = (float*)d_out;

    k_zero<<<1024, 256>>>();
    k_count<<<(EE + 255) / 256, 256>>>(edge_index, edge_type);
    k_w1<<<(NN * HH + 255) / 256, 256>>>(basis1, comp1);
    k_w2<<<(RR * HH * CC + 127) / 128, 128>>>(basis2, comp2);
    {
        long long t = (long long)EE * HH;
        k_scatter1<<<(unsigned)((t + 511) / 512), 512>>>(edge_index, edge_type);
    }
    k_relu<<<(NN * HH + 255) / 256, 256>>>(root1, bias1);
    k_scatter2<<<(EE + 255) / 256, 256>>>(edge_index, edge_type);
    k_final<<<(NN + 127) / 128, 128>>>(root2, bias2, out);
}

// round 4
// speedup vs baseline: 1.2922x; 1.2922x over previous
#include <cuda_runtime.h>
#include <math.h>

#define NN 50000
#define EE 800000
#define RR 32
#define BB 15
#define HH 8
#define CC 16

// ---- scratch (device globals; no allocation allowed) ----
__device__ __align__(16) int   g_counts[NN * RR];              // 6.4 MB
__device__ __align__(16) float g_w1[(size_t)RR * NN * HH];     // 51.2 MB
__device__ __align__(16) float g_w2[RR * HH * CC];             // 16 KB
__device__ __align__(16) float g_norm[EE];                     // 3.2 MB
__device__ __align__(16) float g_agg1[NN * HH];                // 1.6 MB
__device__ __align__(16) float g_x[NN * HH];                   // 1.6 MB
__device__ __align__(16) float g_agg2[NN * CC];                // 3.2 MB

__device__ __forceinline__ void red_add_v4(float* addr, float a, float b,
                                           float c, float d) {
    asm volatile("red.global.add.v4.f32 [%0], {%1,%2,%3,%4};"
                 :: "l"(addr), "f"(a), "f"(b), "f"(c), "f"(d) : "memory");
}

// ---- 1. zero the accumulators ----
__global__ void k_zero() {
    int i = blockIdx.x * blockDim.x + threadIdx.x;
    int stride = gridDim.x * blockDim.x;
    for (int j = i; j < NN * RR; j += stride) g_counts[j] = 0;
    for (int j = i; j < NN * HH; j += stride) g_agg1[j] = 0.0f;
    for (int j = i; j < NN * CC; j += stride) g_agg2[j] = 0.0f;
}

// ---- 2. per-(target, relation) in-degree counts ----
__global__ void k_count(const int* __restrict__ edge_index,
                        const int* __restrict__ edge_type) {
    int e = blockIdx.x * blockDim.x + threadIdx.x;
    if (e >= EE) return;
    int tgt = __ldg(&edge_index[EE + e]);
    int et  = __ldg(&edge_type[e]);
    atomicAdd(&g_counts[tgt * RR + et], 1);
}

// ---- 2b. per-edge normalization factor (coalesced read in scatters) ----
__global__ void k_norm(const int* __restrict__ edge_index,
                       const int* __restrict__ edge_type) {
    int e = blockIdx.x * blockDim.x + threadIdx.x;
    if (e >= EE) return;
    int tgt = __ldg(&edge_index[EE + e]);
    int et  = __ldg(&edge_type[e]);
    float cnt = (float)g_counts[tgt * RR + et];
    g_norm[e] = 1.0f / fmaxf(cnt, 1.0f);
}

// ---- 3. w1[r,n,h] = sum_b comp1[r,b] * basis1[b,n,h] ----
__global__ void k_w1(const float* __restrict__ basis1,
                     const float* __restrict__ comp1) {
    __shared__ float sc[RR * BB];
    for (int i = threadIdx.x; i < RR * BB; i += blockDim.x) sc[i] = comp1[i];
    __syncthreads();
    int idx = blockIdx.x * blockDim.x + threadIdx.x;   // over NN*HH
    if (idx >= NN * HH) return;
    float bv[BB];
#pragma unroll
    for (int b = 0; b < BB; b++) bv[b] = __ldg(&basis1[b * (NN * HH) + idx]);
#pragma unroll 4
    for (int r = 0; r < RR; r++) {
        float s = 0.0f;
#pragma unroll
        for (int b = 0; b < BB; b++) s += sc[r * BB + b] * bv[b];
        g_w1[(size_t)r * (NN * HH) + idx] = s;
    }
}

// ---- 4. w2[r,h,c] = sum_b comp2[r,b] * basis2[b,h,c] (tiny) ----
__global__ void k_w2(const float* __restrict__ basis2,
                     const float* __restrict__ comp2) {
    int idx = blockIdx.x * blockDim.x + threadIdx.x;   // RR*HH*CC = 4096
    if (idx >= RR * HH * CC) return;
    int r  = idx / (HH * CC);
    int hc = idx % (HH * CC);
    float s = 0.0f;
#pragma unroll
    for (int b = 0; b < BB; b++) s += comp2[r * BB + b] * basis2[b * (HH * CC) + hc];
    g_w2[idx] = s;
}

// ---- 5. layer-1 scatter: one thread per edge, 2x red.v4 ----
__global__ void k_scatter1(const int* __restrict__ edge_index,
                           const int* __restrict__ edge_type) {
    int e = blockIdx.x * blockDim.x + threadIdx.x;
    if (e >= EE) return;
    int src = __ldg(&edge_index[e]);
    int tgt = __ldg(&edge_index[EE + e]);
    int et  = __ldg(&edge_type[e]);
    float norm = g_norm[e];
    const float4* wrow = (const float4*)&g_w1[(size_t)et * (NN * HH) + src * HH];
    float4 w0 = wrow[0];
    float4 w1v = wrow[1];
    float* dst = &g_agg1[tgt * HH];
    red_add_v4(dst,     norm * w0.x, norm * w0.y, norm * w0.z, norm * w0.w);
    red_add_v4(dst + 4, norm * w1v.x, norm * w1v.y, norm * w1v.z, norm * w1v.w);
}

// ---- 6a. x = relu(agg1 + root1 + bias1) ----
__global__ void k_relu(const float* __restrict__ root1,
                       const float* __restrict__ bias1) {
    int idx = blockIdx.x * blockDim.x + threadIdx.x;
    if (idx >= NN * HH) return;
    float v = g_agg1[idx] + __ldg(&root1[idx]) + __ldg(&bias1[idx & 7]);
    g_x[idx] = fmaxf(v, 0.0f);
}

// ---- 6b. layer-2 scatter: one thread per edge, 4x red.v4 ----
__global__ void k_scatter2(const int* __restrict__ edge_index,
                           const int* __restrict__ edge_type) {
    __shared__ float sw[RR * HH * CC];   // 16 KB
    for (int i = threadIdx.x; i < RR * HH * CC; i += blockDim.x) sw[i] = g_w2[i];
    __syncthreads();
    int e = blockIdx.x * blockDim.x + threadIdx.x;
    if (e >= EE) return;
    int src = __ldg(&edge_index[e]);
    int tgt = __ldg(&edge_index[EE + e]);
    int et  = __ldg(&edge_type[e]);
    float norm = g_norm[e];
    float4 x0 = *(const float4*)&g_x[src * HH];
    float4 x1 = *(const float4*)&g_x[src * HH + 4];
    float xv[HH] = {x0.x, x0.y, x0.z, x0.w, x1.x, x1.y, x1.z, x1.w};
    const float* w = &sw[et * HH * CC];
    float s[CC];
#pragma unroll
    for (int c = 0; c < CC; c++) {
        float acc = 0.0f;
#pragma unroll
        for (int h = 0; h < HH; h++) acc += xv[h] * w[h * CC + c];
        s[c] = norm * acc;
    }
    float* dst = &g_agg2[tgt * CC];
#pragma unroll
    for (int c = 0; c < CC; c += 4)
        red_add_v4(dst + c, s[c], s[c + 1], s[c + 2], s[c + 3]);
}

// ---- 7. out = log_softmax(agg2 + x @ root2 + bias2) ----
__global__ void k_final(const float* __restrict__ root2,
                        const float* __restrict__ bias2,
                        float* __restrict__ out) {
    __shared__ float sr[HH * CC];
    __shared__ float sb[CC];
    for (int i = threadIdx.x; i < HH * CC; i += blockDim.x) sr[i] = root2[i];
    if (threadIdx.x < CC) sb[threadIdx.x] = bias2[threadIdx.x];
    __syncthreads();
    int n = blockIdx.x * blockDim.x + threadIdx.x;
    if (n >= NN) return;
    float4 x0 = *(const float4*)&g_x[n * HH];
    float4 x1 = *(const float4*)&g_x[n * HH + 4];
    float xv[HH] = {x0.x, x0.y, x0.z, x0.w, x1.x, x1.y, x1.z, x1.w};
    float v[CC];
    float m = -INFINITY;
#pragma unroll
    for (int c = 0; c < CC; c++) {
        float s = g_agg2[n * CC + c] + sb[c];
#pragma unroll
        for (int h = 0; h < HH; h++) s += xv[h] * sr[h * CC + c];
        v[c] = s;
        m = fmaxf(m, s);
    }
    float sum = 0.0f;
#pragma unroll
    for (int c = 0; c < CC; c++) sum += __expf(v[c] - m);
    float lse = m + __logf(sum);
#pragma unroll
    for (int c = 0; c < CC; c++) out[n * CC + c] = v[c] - lse;
}

extern "C" void kernel_launch(void* const* d_in, const int* in_sizes, int n_in,
                              void* d_out, int out_size) {
    const int*   edge_index = (const int*)d_in[0];   // (2, E)
    const int*   edge_type  = (const int*)d_in[1];   // (E,)
    const float* basis1     = (const float*)d_in[2]; // (B, N, H)
    const float* comp1      = (const float*)d_in[3]; // (R, B)
    const float* root1      = (const float*)d_in[4]; // (N, H)
    const float* bias1      = (const float*)d_in[5]; // (H,)
    const float* basis2     = (const float*)d_in[6]; // (B, H, C)
    const float* comp2      = (const float*)d_in[7]; // (R, B)
    const float* root2      = (const float*)d_in[8]; // (H, C)
    const float* bias2      = (const float*)d_in[9]; // (C,)
    float* out = (float*)d_out;

    k_zero<<<1024, 256>>>();
    k_count<<<(EE + 255) / 256, 256>>>(edge_index, edge_type);
    k_norm<<<(EE + 255) / 256, 256>>>(edge_index, edge_type);
    k_w1<<<(NN * HH + 255) / 256, 256>>>(basis1, comp1);
    k_w2<<<(RR * HH * CC + 127) / 128, 128>>>(basis2, comp2);
    k_scatter1<<<(EE + 255) / 256, 256>>>(edge_index, edge_type);
    k_relu<<<(NN * HH + 255) / 256, 256>>>(root1, bias1);
    k_scatter2<<<(EE + 255) / 256, 256>>>(edge_index, edge_type);
    k_final<<<(NN + 127) / 128, 128>>>(root2, bias2, out);
}

// round 5
// speedup vs baseline: 1.3544x; 1.0481x over previous
#include <cuda_runtime.h>
#include <math.h>

#define NN 50000
#define EE 800000
#define RR 32
#define BB 15
#define HH 8
#define CC 16

// ---- scratch (device globals; no allocation allowed) ----
__device__ __align__(16) int   g_counts[NN * RR];              // 6.4 MB
__device__ __align__(16) float g_w1[(size_t)RR * NN * HH];     // 51.2 MB
__device__ __align__(16) float g_w2[RR * HH * CC];             // 16 KB
__device__ __align__(16) float g_norm[EE];                     // 3.2 MB
__device__ __align__(16) float g_agg1[NN * HH];                // 1.6 MB
__device__ __align__(16) float g_x[NN * HH];                   // 1.6 MB
__device__ __align__(16) float g_agg2[NN * CC];                // 3.2 MB

__device__ __forceinline__ void red_add_v4(float* addr, float a, float b,
                                           float c, float d) {
    asm volatile("red.global.add.v4.f32 [%0], {%1,%2,%3,%4};"
                 :: "l"(addr), "f"(a), "f"(b), "f"(c), "f"(d) : "memory");
}

// ---- 1. zero the accumulators (float4 stores) ----
__global__ void k_zero() {
    int i = blockIdx.x * blockDim.x + threadIdx.x;
    int stride = gridDim.x * blockDim.x;
    float4 z4 = make_float4(0.f, 0.f, 0.f, 0.f);
    int4   zi = make_int4(0, 0, 0, 0);
    for (int j = i; j < NN * RR / 4; j += stride) ((int4*)g_counts)[j] = zi;
    for (int j = i; j < NN * HH / 4; j += stride) ((float4*)g_agg1)[j] = z4;
    for (int j = i; j < NN * CC / 4; j += stride) ((float4*)g_agg2)[j] = z4;
}

// ---- 2. per-(target, relation) in-degree counts ----
__global__ void k_count(const int* __restrict__ edge_index,
                        const int* __restrict__ edge_type) {
    int e = blockIdx.x * blockDim.x + threadIdx.x;
    if (e >= EE) return;
    int tgt = __ldg(&edge_index[EE + e]);
    int et  = __ldg(&edge_type[e]);
    atomicAdd(&g_counts[tgt * RR + et], 1);
}

// ---- 3. w1[r,n,h] = sum_b comp1[r,b] * basis1[b,n,h] (float4) ----
__global__ void k_w1(const float* __restrict__ basis1,
                     const float* __restrict__ comp1) {
    __shared__ float sc[RR * BB];
    for (int i = threadIdx.x; i < RR * BB; i += blockDim.x) sc[i] = comp1[i];
    __syncthreads();
    int idx = blockIdx.x * blockDim.x + threadIdx.x;   // over NN*HH/4
    if (idx >= NN * HH / 4) return;
    const float4* b4 = (const float4*)basis1;
    float4 bv[BB];
#pragma unroll
    for (int b = 0; b < BB; b++) bv[b] = __ldg(&b4[b * (NN * HH / 4) + idx]);
    float4* w4 = (float4*)g_w1;
#pragma unroll 4
    for (int r = 0; r < RR; r++) {
        float4 s = make_float4(0.f, 0.f, 0.f, 0.f);
#pragma unroll
        for (int b = 0; b < BB; b++) {
            float c = sc[r * BB + b];
            s.x += c * bv[b].x; s.y += c * bv[b].y;
            s.z += c * bv[b].z; s.w += c * bv[b].w;
        }
        w4[(size_t)r * (NN * HH / 4) + idx] = s;
    }
}

// ---- 4. w2[r,h,c] = sum_b comp2[r,b] * basis2[b,h,c] (tiny) ----
__global__ void k_w2(const float* __restrict__ basis2,
                     const float* __restrict__ comp2) {
    int idx = blockIdx.x * blockDim.x + threadIdx.x;   // RR*HH*CC = 4096
    if (idx >= RR * HH * CC) return;
    int r  = idx / (HH * CC);
    int hc = idx % (HH * CC);
    float s = 0.0f;
#pragma unroll
    for (int b = 0; b < BB; b++) s += comp2[r * BB + b] * basis2[b * (HH * CC) + hc];
    g_w2[idx] = s;
}

// ---- 5. layer-1 scatter (also computes + saves per-edge norm) ----
__global__ void k_scatter1(const int* __restrict__ edge_index,
                           const int* __restrict__ edge_type) {
    int e = blockIdx.x * blockDim.x + threadIdx.x;
    if (e >= EE) return;
    int src = __ldg(&edge_index[e]);
    int tgt = __ldg(&edge_index[EE + e]);
    int et  = __ldg(&edge_type[e]);
    float cnt  = (float)g_counts[tgt * RR + et];
    float norm = 1.0f / fmaxf(cnt, 1.0f);
    g_norm[e] = norm;
    const float4* wrow = (const float4*)&g_w1[(size_t)et * (NN * HH) + src * HH];
    float4 w0 = wrow[0];
    float4 w1v = wrow[1];
    float* dst = &g_agg1[tgt * HH];
    red_add_v4(dst,     norm * w0.x,  norm * w0.y,  norm * w0.z,  norm * w0.w);
    red_add_v4(dst + 4, norm * w1v.x, norm * w1v.y, norm * w1v.z, norm * w1v.w);
}

// ---- 6a. x = relu(agg1 + root1 + bias1) ----
__global__ void k_relu(const float* __restrict__ root1,
                       const float* __restrict__ bias1) {
    int idx = blockIdx.x * blockDim.x + threadIdx.x;
    if (idx >= NN * HH) return;
    float v = g_agg1[idx] + __ldg(&root1[idx]) + __ldg(&bias1[idx & 7]);
    g_x[idx] = fmaxf(v, 0.0f);
}

// ---- 6b. layer-2 scatter: one thread per edge, 4x red.v4 ----
__global__ void k_scatter2(const int* __restrict__ edge_index,
                           const int* __restrict__ edge_type) {
    __shared__ float sw[RR * HH * CC];   // 16 KB
    for (int i = threadIdx.x; i < RR * HH * CC; i += blockDim.x) sw[i] = g_w2[i];
    __syncthreads();
    int e = blockIdx.x * blockDim.x + threadIdx.x;
    if (e >= EE) return;
    int src = __ldg(&edge_index[e]);
    int tgt = __ldg(&edge_index[EE + e]);
    int et  = __ldg(&edge_type[e]);
    float norm = g_norm[e];
    float4 x0 = *(const float4*)&g_x[src * HH];
    float4 x1 = *(const float4*)&g_x[src * HH + 4];
    float xv[HH] = {x0.x, x0.y, x0.z, x0.w, x1.x, x1.y, x1.z, x1.w};
    const float* w = &sw[et * HH * CC];
    float s[CC];
#pragma unroll
    for (int c = 0; c < CC; c++) {
        float acc = 0.0f;
#pragma unroll
        for (int h = 0; h < HH; h++) acc += xv[h] * w[h * CC + c];
        s[c] = norm * acc;
    }
    float* dst = &g_agg2[tgt * CC];
#pragma unroll
    for (int c = 0; c < CC; c += 4)
        red_add_v4(dst + c, s[c], s[c + 1], s[c + 2], s[c + 3]);
}

// ---- 7. out = log_softmax(agg2 + x @ root2 + bias2) ----
__global__ void k_final(const float* __restrict__ root2,
                        const float* __restrict__ bias2,
                        float* __restrict__ out) {
    __shared__ float sr[HH * CC];
    __shared__ float sb[CC];
    for (int i = threadIdx.x; i < HH * CC; i += blockDim.x) sr[i] = root2[i];
    if (threadIdx.x < CC) sb[threadIdx.x] = bias2[threadIdx.x];
    __syncthreads();
    int n = blockIdx.x * blockDim.x + threadIdx.x;
    if (n >= NN) return;
    float4 x0 = *(const float4*)&g_x[n * HH];
    float4 x1 = *(const float4*)&g_x[n * HH + 4];
    float xv[HH] = {x0.x, x0.y, x0.z, x0.w, x1.x, x1.y, x1.z, x1.w};
    float v[CC];
    float m = -INFINITY;
#pragma unroll
    for (int c = 0; c < CC; c++) {
        float s = g_agg2[n * CC + c] + sb[c];
#pragma unroll
        for (int h = 0; h < HH; h++) s += xv[h] * sr[h * CC + c];
        v[c] = s;
        m = fmaxf(m, s);
    }
    float sum = 0.0f;
#pragma unroll
    for (int c = 0; c < CC; c++) sum += __expf(v[c] - m);
    float lse = m + __logf(sum);
#pragma unroll
    for (int c = 0; c < CC; c++) out[n * CC + c] = v[c] - lse;
}

extern "C" void kernel_launch(void* const* d_in, const int* in_sizes, int n_in,
                              void* d_out, int out_size) {
    const int*   edge_index = (const int*)d_in[0];   // (2, E)
    const int*   edge_type  = (const int*)d_in[1];   // (E,)
    const float* basis1     = (const float*)d_in[2]; // (B, N, H)
    const float* comp1      = (const float*)d_in[3]; // (R, B)
    const float* root1      = (const float*)d_in[4]; // (N, H)
    const float* bias1      = (const float*)d_in[5]; // (H,)
    const float* basis2     = (const float*)d_in[6]; // (B, H, C)
    const float* comp2      = (const float*)d_in[7]; // (R, B)
    const float* root2      = (const float*)d_in[8]; // (H, C)
    const float* bias2      = (const float*)d_in[9]; // (C,)
    float* out = (float*)d_out;

    k_zero<<<2048, 256>>>();
    k_count<<<(EE + 511) / 512, 512>>>(edge_index, edge_type);
    k_w1<<<(NN * HH / 4 + 255) / 256, 256>>>(basis1, comp1);
    k_w2<<<(RR * HH * CC + 127) / 128, 128>>>(basis2, comp2);
    k_scatter1<<<(EE + 511) / 512, 512>>>(edge_index, edge_type);
    k_relu<<<(NN * HH + 255) / 256, 256>>>(root1, bias1);
    k_scatter2<<<(EE + 255) / 256, 256>>>(edge_index, edge_type);
    k_final<<<(NN + 127) / 128, 128>>>(root2, bias2, out);
}

// round 6
// speedup vs baseline: 1.3585x; 1.0030x over previous
#include <cuda_runtime.h>
#include <math.h>

#define NN 50000
#define EE 800000
#define RR 32
#define BB 15
#define HH 8
#define CC 16

// ---- scratch (device globals; no allocation allowed) ----
__device__ __align__(16) int   g_counts[NN * RR];              // 6.4 MB
__device__ __align__(16) float g_w1[(size_t)RR * NN * HH];     // 51.2 MB
__device__ __align__(16) float g_w2[RR * HH * CC];             // 16 KB
__device__ __align__(16) float g_norm[EE];                     // 3.2 MB
__device__ __align__(16) float g_agg1[NN * HH];                // 1.6 MB
__device__ __align__(16) float g_x[NN * HH];                   // 1.6 MB
__device__ __align__(16) float g_agg2[NN * CC];                // 3.2 MB

__device__ __forceinline__ void red_add_v4(float* addr, float a, float b,
                                           float c, float d) {
    asm volatile("red.global.add.v4.f32 [%0], {%1,%2,%3,%4};"
                 :: "l"(addr), "f"(a), "f"(b), "f"(c), "f"(d) : "memory");
}

// ---- 0. setup: zero accumulators (float4) + compute tiny w2 ----
__global__ void k_setup(const float* __restrict__ basis2,
                        const float* __restrict__ comp2) {
    int i = blockIdx.x * blockDim.x + threadIdx.x;
    int stride = gridDim.x * blockDim.x;
    if (i < RR * HH * CC) {           // w2[r,h,c] = sum_b comp2[r,b]*basis2[b,h,c]
        int r  = i / (HH * CC);
        int hc = i % (HH * CC);
        float s = 0.0f;
#pragma unroll
        for (int b = 0; b < BB; b++)
            s += comp2[r * BB + b] * basis2[b * (HH * CC) + hc];
        g_w2[i] = s;
    }
    float4 z4 = make_float4(0.f, 0.f, 0.f, 0.f);
    int4   zi = make_int4(0, 0, 0, 0);
    for (int j = i; j < NN * RR / 4; j += stride) ((int4*)g_counts)[j] = zi;
    for (int j = i; j < NN * HH / 4; j += stride) ((float4*)g_agg1)[j] = z4;
    for (int j = i; j < NN * CC / 4; j += stride) ((float4*)g_agg2)[j] = z4;
}

// ---- 1. per-(target, relation) in-degree counts ----
__global__ void k_count(const int* __restrict__ edge_index,
                        const int* __restrict__ edge_type) {
    int e = blockIdx.x * blockDim.x + threadIdx.x;
    if (e >= EE) return;
    int tgt = __ldg(&edge_index[EE + e]);
    int et  = __ldg(&edge_type[e]);
    atomicAdd(&g_counts[tgt * RR + et], 1);
}

// ---- 2. w1[r,n,h] = sum_b comp1[r,b] * basis1[b,n,h] (float4) ----
__global__ void k_w1(const float* __restrict__ basis1,
                     const float* __restrict__ comp1) {
    __shared__ float sc[RR * BB];
    for (int i = threadIdx.x; i < RR * BB; i += blockDim.x) sc[i] = comp1[i];
    __syncthreads();
    int idx = blockIdx.x * blockDim.x + threadIdx.x;   // over NN*HH/4
    if (idx >= NN * HH / 4) return;
    const float4* b4 = (const float4*)basis1;
    float4 bv[BB];
#pragma unroll
    for (int b = 0; b < BB; b++) bv[b] = __ldg(&b4[b * (NN * HH / 4) + idx]);
    float4* w4 = (float4*)g_w1;
#pragma unroll 4
    for (int r = 0; r < RR; r++) {
        float4 s = make_float4(0.f, 0.f, 0.f, 0.f);
#pragma unroll
        for (int b = 0; b < BB; b++) {
            float c = sc[r * BB + b];
            s.x += c * bv[b].x; s.y += c * bv[b].y;
            s.z += c * bv[b].z; s.w += c * bv[b].w;
        }
        w4[(size_t)r * (NN * HH / 4) + idx] = s;
    }
}

// ---- 3. layer-1 scatter (also computes + saves per-edge norm) ----
__global__ void k_scatter1(const int* __restrict__ edge_index,
                           const int* __restrict__ edge_type) {
    int e = blockIdx.x * blockDim.x + threadIdx.x;
    if (e >= EE) return;
    int src = __ldg(&edge_index[e]);
    int tgt = __ldg(&edge_index[EE + e]);
    int et  = __ldg(&edge_type[e]);
    float cnt  = (float)g_counts[tgt * RR + et];
    float norm = 1.0f / fmaxf(cnt, 1.0f);
    g_norm[e] = norm;
    const float4* wrow = (const float4*)&g_w1[(size_t)et * (NN * HH) + src * HH];
    float4 w0 = wrow[0];
    float4 w1v = wrow[1];
    float* dst = &g_agg1[tgt * HH];
    red_add_v4(dst,     norm * w0.x,  norm * w0.y,  norm * w0.z,  norm * w0.w);
    red_add_v4(dst + 4, norm * w1v.x, norm * w1v.y, norm * w1v.z, norm * w1v.w);
}

// ---- 4. x = relu(agg1 + root1 + bias1) ----
__global__ void k_relu(const float* __restrict__ root1,
                       const float* __restrict__ bias1) {
    int idx = blockIdx.x * blockDim.x + threadIdx.x;
    if (idx >= NN * HH) return;
    float v = g_agg1[idx] + __ldg(&root1[idx]) + __ldg(&bias1[idx & 7]);
    g_x[idx] = fmaxf(v, 0.0f);
}

// ---- 5. layer-2 scatter: one thread per edge, 4x red.v4 ----
__global__ void k_scatter2(const int* __restrict__ edge_index,
                           const int* __restrict__ edge_type) {
    __shared__ float sw[RR * HH * CC];   // 16 KB
    for (int i = threadIdx.x; i < RR * HH * CC; i += blockDim.x) sw[i] = g_w2[i];
    __syncthreads();
    int e = blockIdx.x * blockDim.x + threadIdx.x;
    if (e >= EE) return;
    int src = __ldg(&edge_index[e]);
    int tgt = __ldg(&edge_index[EE + e]);
    int et  = __ldg(&edge_type[e]);
    float norm = __ldg(&g_norm[e]);
    float4 x0 = *(const float4*)&g_x[src * HH];
    float4 x1 = *(const float4*)&g_x[src * HH + 4];
    float xv[HH] = {x0.x, x0.y, x0.z, x0.w, x1.x, x1.y, x1.z, x1.w};
    const float* w = &sw[et * HH * CC];
    float s[CC];
#pragma unroll
    for (int c = 0; c < CC; c++) {
        float acc = 0.0f;
#pragma unroll
        for (int h = 0; h < HH; h++) acc += xv[h] * w[h * CC + c];
        s[c] = norm * acc;
    }
    float* dst = &g_agg2[tgt * CC];
#pragma unroll
    for (int c = 0; c < CC; c += 4)
        red_add_v4(dst + c, s[c], s[c + 1], s[c + 2], s[c + 3]);
}

// ---- 6. out = log_softmax(agg2 + x @ root2 + bias2) ----
__global__ void k_final(const float* __restrict__ root2,
                        const float* __restrict__ bias2,
                        float* __restrict__ out) {
    __shared__ float sr[HH * CC];
    __shared__ float sb[CC];
    for (int i = threadIdx.x; i < HH * CC; i += blockDim.x) sr[i] = root2[i];
    if (threadIdx.x < CC) sb[threadIdx.x] = bias2[threadIdx.x];
    __syncthreads();
    int n = blockIdx.x * blockDim.x + threadIdx.x;
    if (n >= NN) return;
    float4 x0 = *(const float4*)&g_x[n * HH];
    float4 x1 = *(const float4*)&g_x[n * HH + 4];
    float xv[HH] = {x0.x, x0.y, x0.z, x0.w, x1.x, x1.y, x1.z, x1.w};
    float v[CC];
    float m = -INFINITY;
#pragma unroll
    for (int c = 0; c < CC; c++) {
        float s = g_agg2[n * CC + c] + sb[c];
#pragma unroll
        for (int h = 0; h < HH; h++) s += xv[h] * sr[h * CC + c];
        v[c] = s;
        m = fmaxf(m, s);
    }
    float sum = 0.0f;
#pragma unroll
    for (int c = 0; c < CC; c++) sum += __expf(v[c] - m);
    float lse = m + __logf(sum);
#pragma unroll
    for (int c = 0; c < CC; c++) out[n * CC + c] = v[c] - lse;
}

extern "C" void kernel_launch(void* const* d_in, const int* in_sizes, int n_in,
                              void* d_out, int out_size) {
    const int*   edge_index = (const int*)d_in[0];   // (2, E)
    const int*   edge_type  = (const int*)d_in[1];   // (E,)
    const float* basis1     = (const float*)d_in[2]; // (B, N, H)
    const float* comp1      = (const float*)d_in[3]; // (R, B)
    const float* root1      = (const float*)d_in[4]; // (N, H)
    const float* bias1      = (const float*)d_in[5]; // (H,)
    const float* basis2     = (const float*)d_in[6]; // (B, H, C)
    const float* comp2      = (const float*)d_in[7]; // (R, B)
    const float* root2      = (const float*)d_in[8]; // (H, C)
    const float* bias2      = (const float*)d_in[9]; // (C,)
    float* out = (float*)d_out;

    k_setup<<<2048, 256>>>(basis2, comp2);                       // idx 0
    k_count<<<(EE + 511) / 512, 512>>>(edge_index, edge_type);   // idx 1
    k_w1<<<(NN * HH / 4 + 255) / 256, 256>>>(basis1, comp1);     // idx 2
    k_scatter1<<<(EE + 511) / 512, 512>>>(edge_index, edge_type);// idx 3 (profiled)
    k_relu<<<(NN * HH + 255) / 256, 256>>>(root1, bias1);        // idx 4
    k_scatter2<<<(EE + 255) / 256, 256>>>(edge_index, edge_type);// idx 5
    k_final<<<(NN + 127) / 128, 128>>>(root2, bias2, out);       // idx 6
}

// round 7
// speedup vs baseline: 2.3926x; 1.7612x over previous
#include <cuda_runtime.h>
#include <math.h>

#define NN 50000
#define EE 800000
#define RR 32
#define BB 15
#define HH 8
#define CC 16
#define WPAD 129   // padded row stride (floats) for w2 in smem: et -> distinct banks

// ---- scratch (device globals; no allocation allowed) ----
__device__ __align__(16) int   g_counts[NN * RR];              // 6.4 MB
__device__ __align__(16) float g_w1[(size_t)RR * NN * HH];     // 51.2 MB
__device__ __align__(16) float g_w2[RR * HH * CC];             // 16 KB
__device__ __align__(16) float g_norm[EE];                     // 3.2 MB
__device__ __align__(16) float g_agg1[NN * HH];                // 1.6 MB
__device__ __align__(16) float g_x[NN * HH];                   // 1.6 MB
__device__ __align__(16) float g_agg2[NN * CC];                // 3.2 MB

__device__ __forceinline__ void red_add_v4(float* addr, float a, float b,
                                           float c, float d) {
    asm volatile("red.global.add.v4.f32 [%0], {%1,%2,%3,%4};"
                 :: "l"(addr), "f"(a), "f"(b), "f"(c), "f"(d) : "memory");
}

// ---- 0. setup: zero accumulators (float4) + compute tiny w2 ----
__global__ void k_setup(const float* __restrict__ basis2,
                        const float* __restrict__ comp2) {
    int i = blockIdx.x * blockDim.x + threadIdx.x;
    int stride = gridDim.x * blockDim.x;
    if (i < RR * HH * CC) {           // w2[r,h,c] = sum_b comp2[r,b]*basis2[b,h,c]
        int r  = i / (HH * CC);
        int hc = i % (HH * CC);
        float s = 0.0f;
#pragma unroll
        for (int b = 0; b < BB; b++)
            s += comp2[r * BB + b] * basis2[b * (HH * CC) + hc];
        g_w2[i] = s;
    }
    float4 z4 = make_float4(0.f, 0.f, 0.f, 0.f);
    int4   zi = make_int4(0, 0, 0, 0);
    for (int j = i; j < NN * RR / 4; j += stride) ((int4*)g_counts)[j] = zi;
    for (int j = i; j < NN * HH / 4; j += stride) ((float4*)g_agg1)[j] = z4;
    for (int j = i; j < NN * CC / 4; j += stride) ((float4*)g_agg2)[j] = z4;
}

// ---- 1. per-(target, relation) in-degree counts ----
__global__ void k_count(const int* __restrict__ edge_index,
                        const int* __restrict__ edge_type) {
    int e = blockIdx.x * blockDim.x + threadIdx.x;
    if (e >= EE) return;
    int tgt = __ldg(&edge_index[EE + e]);
    int et  = __ldg(&edge_type[e]);
    atomicAdd(&g_counts[tgt * RR + et], 1);
}

// ---- 2. w1[r,n,h] = sum_b comp1[r,b] * basis1[b,n,h] (float4) ----
__global__ void k_w1(const float* __restrict__ basis1,
                     const float* __restrict__ comp1) {
    __shared__ float sc[RR * BB];
    for (int i = threadIdx.x; i < RR * BB; i += blockDim.x) sc[i] = comp1[i];
    __syncthreads();
    int idx = blockIdx.x * blockDim.x + threadIdx.x;   // over NN*HH/4
    if (idx >= NN * HH / 4) return;
    const float4* b4 = (const float4*)basis1;
    float4 bv[BB];
#pragma unroll
    for (int b = 0; b < BB; b++) bv[b] = __ldg(&b4[b * (NN * HH / 4) + idx]);
    float4* w4 = (float4*)g_w1;
#pragma unroll 4
    for (int r = 0; r < RR; r++) {
        float4 s = make_float4(0.f, 0.f, 0.f, 0.f);
#pragma unroll
        for (int b = 0; b < BB; b++) {
            float c = sc[r * BB + b];
            s.x += c * bv[b].x; s.y += c * bv[b].y;
            s.z += c * bv[b].z; s.w += c * bv[b].w;
        }
        w4[(size_t)r * (NN * HH / 4) + idx] = s;
    }
}

// ---- 3. layer-1 scatter (also computes + saves per-edge norm) ----
__global__ void k_scatter1(const int* __restrict__ edge_index,
                           const int* __restrict__ edge_type) {
    int e = blockIdx.x * blockDim.x + threadIdx.x;
    if (e >= EE) return;
    int src = __ldg(&edge_index[e]);
    int tgt = __ldg(&edge_index[EE + e]);
    int et  = __ldg(&edge_type[e]);
    float cnt  = (float)g_counts[tgt * RR + et];
    float norm = 1.0f / fmaxf(cnt, 1.0f);
    g_norm[e] = norm;
    const float4* wrow = (const float4*)&g_w1[(size_t)et * (NN * HH) + src * HH];
    float4 w0 = wrow[0];
    float4 w1v = wrow[1];
    float* dst = &g_agg1[tgt * HH];
    red_add_v4(dst,     norm * w0.x,  norm * w0.y,  norm * w0.z,  norm * w0.w);
    red_add_v4(dst + 4, norm * w1v.x, norm * w1v.y, norm * w1v.z, norm * w1v.w);
}

// ---- 4. x = relu(agg1 + root1 + bias1) ----
__global__ void k_relu(const float* __restrict__ root1,
                       const float* __restrict__ bias1) {
    int idx = blockIdx.x * blockDim.x + threadIdx.x;
    if (idx >= NN * HH) return;
    float v = g_agg1[idx] + __ldg(&root1[idx]) + __ldg(&bias1[idx & 7]);
    g_x[idx] = fmaxf(v, 0.0f);
}

// ---- 5. layer-2 scatter: padded smem weights (stride 129 -> conflict-free) ----
__global__ void k_scatter2(const int* __restrict__ edge_index,
                           const int* __restrict__ edge_type) {
    __shared__ float sw[RR * WPAD];   // 32 rows x 129 floats = 16.5 KB
    for (int i = threadIdx.x; i < RR * HH * CC; i += blockDim.x) {
        int r  = i / (HH * CC);
        int hc = i % (HH * CC);
        sw[r * WPAD + hc] = g_w2[i];
    }
    __syncthreads();
    int e = blockIdx.x * blockDim.x + threadIdx.x;
    if (e >= EE) return;
    int src = __ldg(&edge_index[e]);
    int tgt = __ldg(&edge_index[EE + e]);
    int et  = __ldg(&edge_type[e]);
    float norm = __ldg(&g_norm[e]);
    float4 x0 = *(const float4*)&g_x[src * HH];
    float4 x1 = *(const float4*)&g_x[src * HH + 4];
    float xv[HH] = {x0.x, x0.y, x0.z, x0.w, x1.x, x1.y, x1.z, x1.w};
    const float* w = &sw[et * WPAD];
    float s[CC];
#pragma unroll
    for (int c = 0; c < CC; c++) s[c] = 0.0f;
#pragma unroll
    for (int h = 0; h < HH; h++) {
        float xh = xv[h];
#pragma unroll
        for (int c = 0; c < CC; c++) s[c] += xh * w[h * CC + c];
    }
    float* dst = &g_agg2[tgt * CC];
#pragma unroll
    for (int c = 0; c < CC; c += 4)
        red_add_v4(dst + c, norm * s[c], norm * s[c + 1],
                            norm * s[c + 2], norm * s[c + 3]);
}

// ---- 6. out = log_softmax(agg2 + x @ root2 + bias2) ----
__global__ void k_final(const float* __restrict__ root2,
                        const float* __restrict__ bias2,
                        float* __restrict__ out) {
    __shared__ float sr[HH * CC];
    __shared__ float sb[CC];
    for (int i = threadIdx.x; i < HH * CC; i += blockDim.x) sr[i] = root2[i];
    if (threadIdx.x < CC) sb[threadIdx.x] = bias2[threadIdx.x];
    __syncthreads();
    int n = blockIdx.x * blockDim.x + threadIdx.x;
    if (n >= NN) return;
    float4 x0 = *(const float4*)&g_x[n * HH];
    float4 x1 = *(const float4*)&g_x[n * HH + 4];
    float xv[HH] = {x0.x, x0.y, x0.z, x0.w, x1.x, x1.y, x1.z, x1.w};
    float v[CC];
    float m = -INFINITY;
#pragma unroll
    for (int c = 0; c < CC; c++) {
        float s = g_agg2[n * CC + c] + sb[c];
#pragma unroll
        for (int h = 0; h < HH; h++) s += xv[h] * sr[h * CC + c];
        v[c] = s;
        m = fmaxf(m, s);
    }
    float sum = 0.0f;
#pragma unroll
    for (int c = 0; c < CC; c++) sum += __expf(v[c] - m);
    float lse = m + __logf(sum);
#pragma unroll
    for (int c = 0; c < CC; c++) out[n * CC + c] = v[c] - lse;
}

extern "C" void kernel_launch(void* const* d_in, const int* in_sizes, int n_in,
                              void* d_out, int out_size) {
    const int*   edge_index = (const int*)d_in[0];   // (2, E)
    const int*   edge_type  = (const int*)d_in[1];   // (E,)
    const float* basis1     = (const float*)d_in[2]; // (B, N, H)
    const float* comp1      = (const float*)d_in[3]; // (R, B)
    const float* root1      = (const float*)d_in[4]; // (N, H)
    const float* bias1      = (const float*)d_in[5]; // (H,)
    const float* basis2     = (const float*)d_in[6]; // (B, H, C)
    const float* comp2      = (const float*)d_in[7]; // (R, B)
    const float* root2      = (const float*)d_in[8]; // (H, C)
    const float* bias2      = (const float*)d_in[9]; // (C,)
    float* out = (float*)d_out;

    k_setup<<<2048, 256>>>(basis2, comp2);                       // idx 0
    k_count<<<(EE + 511) / 512, 512>>>(edge_index, edge_type);   // idx 1
    k_w1<<<(NN * HH / 4 + 255) / 256, 256>>>(basis1, comp1);     // idx 2
    k_scatter1<<<(EE + 511) / 512, 512>>>(edge_index, edge_type);// idx 3 (profiled)
    k_relu<<<(NN * HH + 255) / 256, 256>>>(root1, bias1);        // idx 4
    k_scatter2<<<(EE + 255) / 256, 256>>>(edge_index, edge_type);// idx 5
    k_final<<<(NN + 127) / 128, 128>>>(root2, bias2, out);       // idx 6
}

// round 8
// speedup vs baseline: 2.4576x; 1.0272x over previous
#include <cuda_runtime.h>
#include <math.h>

#define NN 50000
#define EE 800000
#define RR 32
#define BB 15
#define HH 8
#define CC 16
#define WPAD 129   // padded row stride (floats) for w2 in smem: et -> distinct banks

// ---- scratch (device globals; no allocation allowed) ----
__device__ __align__(16) int   g_counts[NN * RR];              // 6.4 MB
__device__ __align__(16) float g_w1[(size_t)RR * NN * HH];     // 51.2 MB
__device__ __align__(16) float g_w2[RR * HH * CC];             // 16 KB
__device__ __align__(16) float g_norm[EE];                     // 3.2 MB
__device__ __align__(16) float g_agg1[NN * HH];                // 1.6 MB
__device__ __align__(16) float g_x[NN * HH];                   // 1.6 MB
__device__ __align__(16) float g_agg2[NN * CC];                // 3.2 MB

__device__ __forceinline__ void red_add_v4(float* addr, float a, float b,
                                           float c, float d) {
    asm volatile("red.global.add.v4.f32 [%0], {%1,%2,%3,%4};"
                 :: "l"(addr), "f"(a), "f"(b), "f"(c), "f"(d) : "memory");
}

// ---- 0. setup: zero accumulators (float4) + compute tiny w2 ----
__global__ void k_setup(const float* __restrict__ basis2,
                        const float* __restrict__ comp2) {
    int i = blockIdx.x * blockDim.x + threadIdx.x;
    int stride = gridDim.x * blockDim.x;
    if (i < RR * HH * CC) {           // w2[r,h,c] = sum_b comp2[r,b]*basis2[b,h,c]
        int r  = i / (HH * CC);
        int hc = i % (HH * CC);
        float s = 0.0f;
#pragma unroll
        for (int b = 0; b < BB; b++)
            s += comp2[r * BB + b] * basis2[b * (HH * CC) + hc];
        g_w2[i] = s;
    }
    float4 z4 = make_float4(0.f, 0.f, 0.f, 0.f);
    int4   zi = make_int4(0, 0, 0, 0);
    for (int j = i; j < NN * RR / 4; j += stride) ((int4*)g_counts)[j] = zi;
    for (int j = i; j < NN * HH / 4; j += stride) ((float4*)g_agg1)[j] = z4;
    for (int j = i; j < NN * CC / 4; j += stride) ((float4*)g_agg2)[j] = z4;
}

// ---- 1. per-(target, relation) in-degree counts (2 edges/thread) ----
__global__ void k_count(const int* __restrict__ edge_index,
                        const int* __restrict__ edge_type) {
    int p = blockIdx.x * blockDim.x + threadIdx.x;
    if (p >= EE / 2) return;
    int2 tgt = ((const int2*)(edge_index + EE))[p];
    int2 et  = ((const int2*)edge_type)[p];
    atomicAdd(&g_counts[tgt.x * RR + et.x], 1);
    atomicAdd(&g_counts[tgt.y * RR + et.y], 1);
}

// ---- 2. w1[r,n,h] = sum_b comp1[r,b] * basis1[b,n,h] (float4) ----
__global__ void k_w1(const float* __restrict__ basis1,
                     const float* __restrict__ comp1) {
    __shared__ float sc[RR * BB];
    for (int i = threadIdx.x; i < RR * BB; i += blockDim.x) sc[i] = comp1[i];
    __syncthreads();
    int idx = blockIdx.x * blockDim.x + threadIdx.x;   // over NN*HH/4
    if (idx >= NN * HH / 4) return;
    const float4* b4 = (const float4*)basis1;
    float4 bv[BB];
#pragma unroll
    for (int b = 0; b < BB; b++) bv[b] = __ldg(&b4[b * (NN * HH / 4) + idx]);
    float4* w4 = (float4*)g_w1;
#pragma unroll 4
    for (int r = 0; r < RR; r++) {
        float4 s = make_float4(0.f, 0.f, 0.f, 0.f);
#pragma unroll
        for (int b = 0; b < BB; b++) {
            float c = sc[r * BB + b];
            s.x += c * bv[b].x; s.y += c * bv[b].y;
            s.z += c * bv[b].z; s.w += c * bv[b].w;
        }
        w4[(size_t)r * (NN * HH / 4) + idx] = s;
    }
}

// ---- 3. layer-1 scatter, 2 edges/thread (saves per-edge norm) ----
__global__ void k_scatter1(const int* __restrict__ edge_index,
                           const int* __restrict__ edge_type) {
    int p = blockIdx.x * blockDim.x + threadIdx.x;
    if (p >= EE / 2) return;
    int2 src = ((const int2*)edge_index)[p];
    int2 tgt = ((const int2*)(edge_index + EE))[p];
    int2 et  = ((const int2*)edge_type)[p];
    // two independent count gathers (MLP)
    float c0 = (float)g_counts[tgt.x * RR + et.x];
    float c1 = (float)g_counts[tgt.y * RR + et.y];
    float n0 = 1.0f / fmaxf(c0, 1.0f);
    float n1 = 1.0f / fmaxf(c1, 1.0f);
    ((float2*)g_norm)[p] = make_float2(n0, n1);
    // two independent w1 row gathers
    const float4* wa = (const float4*)&g_w1[(size_t)et.x * (NN * HH) + src.x * HH];
    const float4* wb = (const float4*)&g_w1[(size_t)et.y * (NN * HH) + src.y * HH];
    float4 a0 = wa[0], a1 = wa[1];
    float4 b0 = wb[0], b1 = wb[1];
    float* d0 = &g_agg1[tgt.x * HH];
    float* d1 = &g_agg1[tgt.y * HH];
    red_add_v4(d0,     n0 * a0.x, n0 * a0.y, n0 * a0.z, n0 * a0.w);
    red_add_v4(d0 + 4, n0 * a1.x, n0 * a1.y, n0 * a1.z, n0 * a1.w);
    red_add_v4(d1,     n1 * b0.x, n1 * b0.y, n1 * b0.z, n1 * b0.w);
    red_add_v4(d1 + 4, n1 * b1.x, n1 * b1.y, n1 * b1.z, n1 * b1.w);
}

// ---- 4. x = relu(agg1 + root1 + bias1) ----
__global__ void k_relu(const float* __restrict__ root1,
                       const float* __restrict__ bias1) {
    int idx = blockIdx.x * blockDim.x + threadIdx.x;
    if (idx >= NN * HH) return;
    float v = g_agg1[idx] + __ldg(&root1[idx]) + __ldg(&bias1[idx & 7]);
    g_x[idx] = fmaxf(v, 0.0f);
}

// ---- 5. layer-2 scatter: 2 edges/thread, padded conflict-free smem ----
__global__ void k_scatter2(const int* __restrict__ edge_index,
                           const int* __restrict__ edge_type) {
    __shared__ float sw[RR * WPAD];   // 32 x 129 floats = 16.5 KB
    for (int i = threadIdx.x; i < RR * HH * CC; i += blockDim.x) {
        int r  = i / (HH * CC);
        int hc = i % (HH * CC);
        sw[r * WPAD + hc] = g_w2[i];
    }
    __syncthreads();
    int p = blockIdx.x * blockDim.x + threadIdx.x;
    if (p >= EE / 2) return;
    int2 src = ((const int2*)edge_index)[p];
    int2 tgt = ((const int2*)(edge_index + EE))[p];
    int2 et  = ((const int2*)edge_type)[p];
    float2 nm = ((const float2*)g_norm)[p];
    // two independent x-row gathers
    float4 xa0 = *(const float4*)&g_x[src.x * HH];
    float4 xa1 = *(const float4*)&g_x[src.x * HH + 4];
    float4 xb0 = *(const float4*)&g_x[src.y * HH];
    float4 xb1 = *(const float4*)&g_x[src.y * HH + 4];
    float xva[HH] = {xa0.x, xa0.y, xa0.z, xa0.w, xa1.x, xa1.y, xa1.z, xa1.w};
    float xvb[HH] = {xb0.x, xb0.y, xb0.z, xb0.w, xb1.x, xb1.y, xb1.z, xb1.w};
    const float* wa = &sw[et.x * WPAD];
    const float* wb = &sw[et.y * WPAD];
    float sa[CC], sb[CC];
#pragma unroll
    for (int c = 0; c < CC; c++) { sa[c] = 0.0f; sb[c] = 0.0f; }
#pragma unroll
    for (int h = 0; h < HH; h++) {
        float xh0 = xva[h], xh1 = xvb[h];
#pragma unroll
        for (int c = 0; c < CC; c++) {
            sa[c] += xh0 * wa[h * CC + c];
            sb[c] += xh1 * wb[h * CC + c];
        }
    }
    float* d0 = &g_agg2[tgt.x * CC];
    float* d1 = &g_agg2[tgt.y * CC];
#pragma unroll
    for (int c = 0; c < CC; c += 4)
        red_add_v4(d0 + c, nm.x * sa[c], nm.x * sa[c + 1],
                           nm.x * sa[c + 2], nm.x * sa[c + 3]);
#pragma unroll
    for (int c = 0; c < CC; c += 4)
        red_add_v4(d1 + c, nm.y * sb[c], nm.y * sb[c + 1],
                           nm.y * sb[c + 2], nm.y * sb[c + 3]);
}

// ---- 6. out = log_softmax(agg2 + x @ root2 + bias2) ----
__global__ void k_final(const float* __restrict__ root2,
                        const float* __restrict__ bias2,
                        float* __restrict__ out) {
    __shared__ float sr[HH * CC];
    __shared__ float sb[CC];
    for (int i = threadIdx.x; i < HH * CC; i += blockDim.x) sr[i] = root2[i];
    if (threadIdx.x < CC) sb[threadIdx.x] = bias2[threadIdx.x];
    __syncthreads();
    int n = blockIdx.x * blockDim.x + threadIdx.x;
    if (n >= NN) return;
    float4 x0 = *(const float4*)&g_x[n * HH];
    float4 x1 = *(const float4*)&g_x[n * HH + 4];
    float xv[HH] = {x0.x, x0.y, x0.z, x0.w, x1.x, x1.y, x1.z, x1.w};
    float v[CC];
    float m = -INFINITY;
#pragma unroll
    for (int c = 0; c < CC; c++) {
        float s = g_agg2[n * CC + c] + sb[c];
#pragma unroll
        for (int h = 0; h < HH; h++) s += xv[h] * sr[h * CC + c];
        v[c] = s;
        m = fmaxf(m, s);
    }
    float sum = 0.0f;
#pragma unroll
    for (int c = 0; c < CC; c++) sum += __expf(v[c] - m);
    float lse = m + __logf(sum);
#pragma unroll
    for (int c = 0; c < CC; c++) out[n * CC + c] = v[c] - lse;
}

extern "C" void kernel_launch(void* const* d_in, const int* in_sizes, int n_in,
                              void* d_out, int out_size) {
    const int*   edge_index = (const int*)d_in[0];   // (2, E)
    const int*   edge_type  = (const int*)d_in[1];   // (E,)
    const float* basis1     = (const float*)d_in[2]; // (B, N, H)
    const float* comp1      = (const float*)d_in[3]; // (R, B)
    const float* root1      = (const float*)d_in[4]; // (N, H)
    const float* bias1      = (const float*)d_in[5]; // (H,)
    const float* basis2     = (const float*)d_in[6]; // (B, H, C)
    const float* comp2      = (const float*)d_in[7]; // (R, B)
    const float* root2      = (const float*)d_in[8]; // (H, C)
    const float* bias2      = (const float*)d_in[9]; // (C,)
    float* out = (float*)d_out;

    k_setup<<<2048, 256>>>(basis2, comp2);                            // idx 0
    k_count<<<(EE / 2 + 511) / 512, 512>>>(edge_index, edge_type);    // idx 1
    k_w1<<<(NN * HH / 4 + 255) / 256, 256>>>(basis1, comp1);          // idx 2
    k_scatter1<<<(EE / 2 + 255) / 256, 256>>>(edge_index, edge_type); // idx 3 (profiled)
    k_relu<<<(NN * HH + 255) / 256, 256>>>(root1, bias1);             // idx 4
    k_scatter2<<<(EE / 2 + 255) / 256, 256>>>(edge_index, edge_type); // idx 5
    k_final<<<(NN + 127) / 128, 128>>>(root2, bias2, out);            // idx 6
}

// round 9
// speedup vs baseline: 2.5860x; 1.0522x over previous
#include <cuda_runtime.h>
#include <math.h>

#define NN 50000
#define EE 800000
#define RR 32
#define BB 15
#define HH 8
#define CC 16
#define WPAD 129   // padded row stride (floats) for w2 in smem: et -> distinct banks

// ---- scratch (device globals; no allocation allowed) ----
__device__ __align__(16) int   g_counts[NN * RR];              // 6.4 MB
__device__ __align__(16) float g_w1[(size_t)RR * NN * HH];     // 51.2 MB
__device__ __align__(16) float g_w2[RR * HH * CC];             // 16 KB
__device__ __align__(16) float g_norm[EE];                     // 3.2 MB
__device__ __align__(16) float g_agg1[NN * HH];                // 1.6 MB
__device__ __align__(16) float g_x[NN * HH];                   // 1.6 MB
__device__ __align__(16) float g_agg2[NN * CC];                // 3.2 MB

__device__ __forceinline__ void red_add_v4(float* addr, float a, float b,
                                           float c, float d) {
    asm volatile("red.global.add.v4.f32 [%0], {%1,%2,%3,%4};"
                 :: "l"(addr), "f"(a), "f"(b), "f"(c), "f"(d) : "memory");
}

// ---- 0. setup: zero counts/agg2, pre-bias agg1 with root1+bias1, tiny w2 ----
__global__ void k_setup(const float* __restrict__ basis2,
                        const float* __restrict__ comp2,
                        const float* __restrict__ root1,
                        const float* __restrict__ bias1) {
    int i = blockIdx.x * blockDim.x + threadIdx.x;
    int stride = gridDim.x * blockDim.x;
    if (i < RR * HH * CC) {           // w2[r,h,c] = sum_b comp2[r,b]*basis2[b,h,c]
        int r  = i / (HH * CC);
        int hc = i % (HH * CC);
        float s = 0.0f;
#pragma unroll
        for (int b = 0; b < BB; b++)
            s += comp2[r * BB + b] * basis2[b * (HH * CC) + hc];
        g_w2[i] = s;
    }
    float4 z4 = make_float4(0.f, 0.f, 0.f, 0.f);
    int4   zi = make_int4(0, 0, 0, 0);
    for (int j = i; j < NN * RR / 4; j += stride) ((int4*)g_counts)[j] = zi;
    for (int j = i; j < NN * CC / 4; j += stride) ((float4*)g_agg2)[j] = z4;
    // agg1 := root1 + bias1 (so scatter1 adds messages on top; relu = max+store)
    const float4* r4 = (const float4*)root1;
    float b0 = bias1[0], b1 = bias1[1], b2 = bias1[2], b3 = bias1[3];
    float b4v = bias1[4], b5 = bias1[5], b6 = bias1[6], b7 = bias1[7];
    for (int j = i; j < NN * HH / 4; j += stride) {
        float4 v = r4[j];
        if ((j & 1) == 0) { v.x += b0; v.y += b1; v.z += b2; v.w += b3; }
        else              { v.x += b4v; v.y += b5; v.z += b6; v.w += b7; }
        ((float4*)g_agg1)[j] = v;
    }
}

// ---- 1. FUSED: per-(tgt,rel) counts (all threads) + w1 materialize (low ids) ----
__global__ void k_cw1(const int* __restrict__ edge_index,
                      const int* __restrict__ edge_type,
                      const float* __restrict__ basis1,
                      const float* __restrict__ comp1) {
    __shared__ float sc[RR * BB];
    int p = blockIdx.x * blockDim.x + threadIdx.x;
    bool w1block = (blockIdx.x * blockDim.x) < (NN * HH / 4);
    if (w1block) {
        for (int i = threadIdx.x; i < RR * BB; i += blockDim.x) sc[i] = comp1[i];
        __syncthreads();
    }
    // counts: 2 edges per thread
    if (p < EE / 2) {
        int2 tgt = ((const int2*)(edge_index + EE))[p];
        int2 et  = ((const int2*)edge_type)[p];
        atomicAdd(&g_counts[tgt.x * RR + et.x], 1);
        atomicAdd(&g_counts[tgt.y * RR + et.y], 1);
    }
    // w1: float4 quad per thread for first NN*HH/4 threads
    if (p < NN * HH / 4) {
        const float4* b4 = (const float4*)basis1;
        float4 bv[BB];
#pragma unroll
        for (int b = 0; b < BB; b++) bv[b] = __ldg(&b4[b * (NN * HH / 4) + p]);
        float4* w4 = (float4*)g_w1;
#pragma unroll 4
        for (int r = 0; r < RR; r++) {
            float4 s = make_float4(0.f, 0.f, 0.f, 0.f);
#pragma unroll
            for (int b = 0; b < BB; b++) {
                float c = sc[r * BB + b];
                s.x += c * bv[b].x; s.y += c * bv[b].y;
                s.z += c * bv[b].z; s.w += c * bv[b].w;
            }
            w4[(size_t)r * (NN * HH / 4) + p] = s;
        }
    }
}

// ---- 2. layer-1 scatter, 2 edges/thread (saves per-edge norm) ----
__global__ void k_scatter1(const int* __restrict__ edge_index,
                           const int* __restrict__ edge_type) {
    int p = blockIdx.x * blockDim.x + threadIdx.x;
    if (p >= EE / 2) return;
    int2 src = ((const int2*)edge_index)[p];
    int2 tgt = ((const int2*)(edge_index + EE))[p];
    int2 et  = ((const int2*)edge_type)[p];
    float c0 = (float)g_counts[tgt.x * RR + et.x];
    float c1 = (float)g_counts[tgt.y * RR + et.y];
    float n0 = 1.0f / fmaxf(c0, 1.0f);
    float n1 = 1.0f / fmaxf(c1, 1.0f);
    ((float2*)g_norm)[p] = make_float2(n0, n1);
    const float4* wa = (const float4*)&g_w1[(size_t)et.x * (NN * HH) + src.x * HH];
    const float4* wb = (const float4*)&g_w1[(size_t)et.y * (NN * HH) + src.y * HH];
    float4 a0 = wa[0], a1 = wa[1];
    float4 b0 = wb[0], b1 = wb[1];
    float* d0 = &g_agg1[tgt.x * HH];
    float* d1 = &g_agg1[tgt.y * HH];
    red_add_v4(d0,     n0 * a0.x, n0 * a0.y, n0 * a0.z, n0 * a0.w);
    red_add_v4(d0 + 4, n0 * a1.x, n0 * a1.y, n0 * a1.z, n0 * a1.w);
    red_add_v4(d1,     n1 * b0.x, n1 * b0.y, n1 * b0.z, n1 * b0.w);
    red_add_v4(d1 + 4, n1 * b1.x, n1 * b1.y, n1 * b1.z, n1 * b1.w);
}

// ---- 3. x = relu(agg1)  (agg1 was pre-biased with root1+bias1) ----
__global__ void k_relu() {
    int idx = blockIdx.x * blockDim.x + threadIdx.x;
    if (idx >= NN * HH / 4) return;
    float4 v = ((const float4*)g_agg1)[idx];
    v.x = fmaxf(v.x, 0.0f); v.y = fmaxf(v.y, 0.0f);
    v.z = fmaxf(v.z, 0.0f); v.w = fmaxf(v.w, 0.0f);
    ((float4*)g_x)[idx] = v;
}

// ---- 4. layer-2 scatter: 2 edges/thread, padded conflict-free smem ----
__global__ void k_scatter2(const int* __restrict__ edge_index,
                           const int* __restrict__ edge_type) {
    __shared__ float sw[RR * WPAD];   // 32 x 129 floats = 16.5 KB
    for (int i = threadIdx.x; i < RR * HH * CC; i += blockDim.x) {
        int r  = i / (HH * CC);
        int hc = i % (HH * CC);
        sw[r * WPAD + hc] = g_w2[i];
    }
    __syncthreads();
    int p = blockIdx.x * blockDim.x + threadIdx.x;
    if (p >= EE / 2) return;
    int2 src = ((const int2*)edge_index)[p];
    int2 tgt = ((const int2*)(edge_index + EE))[p];
    int2 et  = ((const int2*)edge_type)[p];
    float2 nm = ((const float2*)g_norm)[p];
    float4 xa0 = *(const float4*)&g_x[src.x * HH];
    float4 xa1 = *(const float4*)&g_x[src.x * HH + 4];
    float4 xb0 = *(const float4*)&g_x[src.y * HH];
    float4 xb1 = *(const float4*)&g_x[src.y * HH + 4];
    float xva[HH] = {xa0.x, xa0.y, xa0.z, xa0.w, xa1.x, xa1.y, xa1.z, xa1.w};
    float xvb[HH] = {xb0.x, xb0.y, xb0.z, xb0.w, xb1.x, xb1.y, xb1.z, xb1.w};
    const float* wa = &sw[et.x * WPAD];
    const float* wb = &sw[et.y * WPAD];
    float sa[CC], sb[CC];
#pragma unroll
    for (int c = 0; c < CC; c++) { sa[c] = 0.0f; sb[c] = 0.0f; }
#pragma unroll
    for (int h = 0; h < HH; h++) {
        float xh0 = xva[h], xh1 = xvb[h];
#pragma unroll
        for (int c = 0; c < CC; c++) {
            sa[c] += xh0 * wa[h * CC + c];
            sb[c] += xh1 * wb[h * CC + c];
        }
    }
    float* d0 = &g_agg2[tgt.x * CC];
    float* d1 = &g_agg2[tgt.y * CC];
#pragma unroll
    for (int c = 0; c < CC; c += 4)
        red_add_v4(d0 + c, nm.x * sa[c], nm.x * sa[c + 1],
                           nm.x * sa[c + 2], nm.x * sa[c + 3]);
#pragma unroll
    for (int c = 0; c < CC; c += 4)
        red_add_v4(d1 + c, nm.y * sb[c], nm.y * sb[c + 1],
                           nm.y * sb[c + 2], nm.y * sb[c + 3]);
}

// ---- 5. out = log_softmax(agg2 + x @ root2 + bias2) ----
__global__ void k_final(const float* __restrict__ root2,
                        const float* __restrict__ bias2,
                        float* __restrict__ out) {
    __shared__ float sr[HH * CC];
    __shared__ float sb[CC];
    for (int i = threadIdx.x; i < HH * CC; i += blockDim.x) sr[i] = root2[i];
    if (threadIdx.x < CC) sb[threadIdx.x] = bias2[threadIdx.x];
    __syncthreads();
    int n = blockIdx.x * blockDim.x + threadIdx.x;
    if (n >= NN) return;
    float4 x0 = *(const float4*)&g_x[n * HH];
    float4 x1 = *(const float4*)&g_x[n * HH + 4];
    float xv[HH] = {x0.x, x0.y, x0.z, x0.w, x1.x, x1.y, x1.z, x1.w};
    float v[CC];
    float m = -INFINITY;
#pragma unroll
    for (int c = 0; c < CC; c++) {
        float s = g_agg2[n * CC + c] + sb[c];
#pragma unroll
        for (int h = 0; h < HH; h++) s += xv[h] * sr[h * CC + c];
        v[c] = s;
        m = fmaxf(m, s);
    }
    float sum = 0.0f;
#pragma unroll
    for (int c = 0; c < CC; c++) sum += __expf(v[c] - m);
    float lse = m + __logf(sum);
#pragma unroll
    for (int c = 0; c < CC; c++) out[n * CC + c] = v[c] - lse;
}

extern "C" void kernel_launch(void* const* d_in, const int* in_sizes, int n_in,
                              void* d_out, int out_size) {
    const int*   edge_index = (const int*)d_in[0];   // (2, E)
    const int*   edge_type  = (const int*)d_in[1];   // (E,)
    const float* basis1     = (const float*)d_in[2]; // (B, N, H)
    const float* comp1      = (const float*)d_in[3]; // (R, B)
    const float* root1      = (const float*)d_in[4]; // (N, H)
    const float* bias1      = (const float*)d_in[5]; // (H,)
    const float* basis2     = (const float*)d_in[6]; // (B, H, C)
    const float* comp2      = (const float*)d_in[7]; // (R, B)
    const float* root2      = (const float*)d_in[8]; // (H, C)
    const float* bias2      = (const float*)d_in[9]; // (C,)
    float* out = (float*)d_out;

    k_setup<<<2048, 256>>>(basis2, comp2, root1, bias1);               // idx 0
    k_cw1<<<(EE / 2 + 255) / 256, 256>>>(edge_index, edge_type,
                                         basis1, comp1);               // idx 1
    k_scatter1<<<(EE / 2 + 255) / 256, 256>>>(edge_index, edge_type);  // idx 2
    k_relu<<<(NN * HH / 4 + 255) / 256, 256>>>();                      // idx 3
    k_scatter2<<<(EE / 2 + 255) / 256, 256>>>(edge_index, edge_type);  // idx 4
    k_final<<<(NN + 127) / 128, 128>>>(root2, bias2, out);             // idx 5
}

// round 10
// speedup vs baseline: 2.6548x; 1.0266x over previous
#include <cuda_runtime.h>
#include <math.h>

#define NN 50000
#define EE 800000
#define RR 32
#define BB 15
#define HH 8
#define CC 16
#define WPAD 129   // padded row stride (floats) for w2 in smem: et -> distinct banks

// ---- scratch (device globals; no allocation allowed) ----
__device__ __align__(16) int   g_counts[NN * RR];              // 6.4 MB
__device__ __align__(16) float g_w1[(size_t)RR * NN * HH];     // 51.2 MB
__device__ __align__(16) float g_w2[RR * HH * CC];             // 16 KB
__device__ __align__(16) float g_norm[EE];                     // 3.2 MB
__device__ __align__(16) float g_agg1[NN * HH];                // 1.6 MB (pre-relu x)
__device__ __align__(16) float g_agg2[NN * CC];                // 3.2 MB

__device__ __forceinline__ void red_add_v4(float* addr, float a, float b,
                                           float c, float d) {
    asm volatile("red.global.add.v4.f32 [%0], {%1,%2,%3,%4};"
                 :: "l"(addr), "f"(a), "f"(b), "f"(c), "f"(d) : "memory");
}

// ---- 0. setup: zero counts/agg2, pre-bias agg1 with root1+bias1, tiny w2 ----
__global__ void k_setup(const float* __restrict__ basis2,
                        const float* __restrict__ comp2,
                        const float* __restrict__ root1,
                        const float* __restrict__ bias1) {
    int i = blockIdx.x * blockDim.x + threadIdx.x;
    int stride = gridDim.x * blockDim.x;
    if (i < RR * HH * CC) {           // w2[r,h,c] = sum_b comp2[r,b]*basis2[b,h,c]
        int r  = i / (HH * CC);
        int hc = i % (HH * CC);
        float s = 0.0f;
#pragma unroll
        for (int b = 0; b < BB; b++)
            s += comp2[r * BB + b] * basis2[b * (HH * CC) + hc];
        g_w2[i] = s;
    }
    float4 z4 = make_float4(0.f, 0.f, 0.f, 0.f);
    int4   zi = make_int4(0, 0, 0, 0);
    for (int j = i; j < NN * RR / 4; j += stride) ((int4*)g_counts)[j] = zi;
    for (int j = i; j < NN * CC / 4; j += stride) ((float4*)g_agg2)[j] = z4;
    // agg1 := root1 + bias1 (scatter1 REDs messages on top; relu applied on read)
    const float4* r4 = (const float4*)root1;
    float b0 = bias1[0], b1 = bias1[1], b2 = bias1[2], b3 = bias1[3];
    float b4v = bias1[4], b5 = bias1[5], b6 = bias1[6], b7 = bias1[7];
    for (int j = i; j < NN * HH / 4; j += stride) {
        float4 v = r4[j];
        if ((j & 1) == 0) { v.x += b0; v.y += b1; v.z += b2; v.w += b3; }
        else              { v.x += b4v; v.y += b5; v.z += b6; v.w += b7; }
        ((float4*)g_agg1)[j] = v;
    }
}

// ---- 1. FUSED: per-(tgt,rel) counts (all threads) + w1 materialize (low ids) ----
__global__ void k_cw1(const int* __restrict__ edge_index,
                      const int* __restrict__ edge_type,
                      const float* __restrict__ basis1,
                      const float* __restrict__ comp1) {
    __shared__ float sc[RR * BB];
    int p = blockIdx.x * blockDim.x + threadIdx.x;
    bool w1block = (blockIdx.x * blockDim.x) < (NN * HH / 4);
    if (w1block) {
        for (int i = threadIdx.x; i < RR * BB; i += blockDim.x) sc[i] = comp1[i];
        __syncthreads();
    }
    if (p < EE / 2) {
        int2 tgt = ((const int2*)(edge_index + EE))[p];
        int2 et  = ((const int2*)edge_type)[p];
        atomicAdd(&g_counts[tgt.x * RR + et.x], 1);
        atomicAdd(&g_counts[tgt.y * RR + et.y], 1);
    }
    if (p < NN * HH / 4) {
        const float4* b4 = (const float4*)basis1;
        float4 bv[BB];
#pragma unroll
        for (int b = 0; b < BB; b++) bv[b] = __ldg(&b4[b * (NN * HH / 4) + p]);
        float4* w4 = (float4*)g_w1;
#pragma unroll 4
        for (int r = 0; r < RR; r++) {
            float4 s = make_float4(0.f, 0.f, 0.f, 0.f);
#pragma unroll
            for (int b = 0; b < BB; b++) {
                float c = sc[r * BB + b];
                s.x += c * bv[b].x; s.y += c * bv[b].y;
                s.z += c * bv[b].z; s.w += c * bv[b].w;
            }
            w4[(size_t)r * (NN * HH / 4) + p] = s;
        }
    }
}

// ---- 2. layer-1 scatter, 2 edges/thread (saves per-edge norm) ----
__global__ void k_scatter1(const int* __restrict__ edge_index,
                           const int* __restrict__ edge_type) {
    int p = blockIdx.x * blockDim.x + threadIdx.x;
    if (p >= EE / 2) return;
    int2 src = ((const int2*)edge_index)[p];
    int2 tgt = ((const int2*)(edge_index + EE))[p];
    int2 et  = ((const int2*)edge_type)[p];
    float c0 = (float)g_counts[tgt.x * RR + et.x];
    float c1 = (float)g_counts[tgt.y * RR + et.y];
    float n0 = 1.0f / fmaxf(c0, 1.0f);
    float n1 = 1.0f / fmaxf(c1, 1.0f);
    ((float2*)g_norm)[p] = make_float2(n0, n1);
    const float4* wa = (const float4*)&g_w1[(size_t)et.x * (NN * HH) + src.x * HH];
    const float4* wb = (const float4*)&g_w1[(size_t)et.y * (NN * HH) + src.y * HH];
    float4 a0 = wa[0], a1 = wa[1];
    float4 b0 = wb[0], b1 = wb[1];
    float* d0 = &g_agg1[tgt.x * HH];
    float* d1 = &g_agg1[tgt.y * HH];
    red_add_v4(d0,     n0 * a0.x, n0 * a0.y, n0 * a0.z, n0 * a0.w);
    red_add_v4(d0 + 4, n0 * a1.x, n0 * a1.y, n0 * a1.z, n0 * a1.w);
    red_add_v4(d1,     n1 * b0.x, n1 * b0.y, n1 * b0.z, n1 * b0.w);
    red_add_v4(d1 + 4, n1 * b1.x, n1 * b1.y, n1 * b1.z, n1 * b1.w);
}

// ---- 3. layer-2 scatter: 2 edges/thread, relu applied on gather ----
__global__ void k_scatter2(const int* __restrict__ edge_index,
                           const int* __restrict__ edge_type) {
    __shared__ float sw[RR * WPAD];   // 32 x 129 floats = 16.5 KB
    for (int i = threadIdx.x; i < RR * HH * CC; i += blockDim.x) {
        int r  = i / (HH * CC);
        int hc = i % (HH * CC);
        sw[r * WPAD + hc] = g_w2[i];
    }
    __syncthreads();
    int p = blockIdx.x * blockDim.x + threadIdx.x;
    if (p >= EE / 2) return;
    int2 src = ((const int2*)edge_index)[p];
    int2 tgt = ((const int2*)(edge_index + EE))[p];
    int2 et  = ((const int2*)edge_type)[p];
    float2 nm = ((const float2*)g_norm)[p];
    float4 xa0 = *(const float4*)&g_agg1[src.x * HH];
    float4 xa1 = *(const float4*)&g_agg1[src.x * HH + 4];
    float4 xb0 = *(const float4*)&g_agg1[src.y * HH];
    float4 xb1 = *(const float4*)&g_agg1[src.y * HH + 4];
    float xva[HH] = {fmaxf(xa0.x,0.f), fmaxf(xa0.y,0.f), fmaxf(xa0.z,0.f), fmaxf(xa0.w,0.f),
                     fmaxf(xa1.x,0.f), fmaxf(xa1.y,0.f), fmaxf(xa1.z,0.f), fmaxf(xa1.w,0.f)};
    float xvb[HH] = {fmaxf(xb0.x,0.f), fmaxf(xb0.y,0.f), fmaxf(xb0.z,0.f), fmaxf(xb0.w,0.f),
                     fmaxf(xb1.x,0.f), fmaxf(xb1.y,0.f), fmaxf(xb1.z,0.f), fmaxf(xb1.w,0.f)};
    const float* wa = &sw[et.x * WPAD];
    const float* wb = &sw[et.y * WPAD];
    float sa[CC], sb[CC];
#pragma unroll
    for (int c = 0; c < CC; c++) { sa[c] = 0.0f; sb[c] = 0.0f; }
#pragma unroll
    for (int h = 0; h < HH; h++) {
        float xh0 = xva[h], xh1 = xvb[h];
#pragma unroll
        for (int c = 0; c < CC; c++) {
            sa[c] += xh0 * wa[h * CC + c];
            sb[c] += xh1 * wb[h * CC + c];
        }
    }
    float* d0 = &g_agg2[tgt.x * CC];
    float* d1 = &g_agg2[tgt.y * CC];
#pragma unroll
    for (int c = 0; c < CC; c += 4)
        red_add_v4(d0 + c, nm.x * sa[c], nm.x * sa[c + 1],
                           nm.x * sa[c + 2], nm.x * sa[c + 3]);
#pragma unroll
    for (int c = 0; c < CC; c += 4)
        red_add_v4(d1 + c, nm.y * sb[c], nm.y * sb[c + 1],
                           nm.y * sb[c + 2], nm.y * sb[c + 3]);
}

// ---- 4. out = log_softmax(agg2 + relu(agg1) @ root2 + bias2) ----
__global__ void k_final(const float* __restrict__ root2,
                        const float* __restrict__ bias2,
                        float* __restrict__ out) {
    __shared__ float sr[HH * CC];
    __shared__ float sb[CC];
    for (int i = threadIdx.x; i < HH * CC; i += blockDim.x) sr[i] = root2[i];
    if (threadIdx.x < CC) sb[threadIdx.x] = bias2[threadIdx.x];
    __syncthreads();
    int n = blockIdx.x * blockDim.x + threadIdx.x;
    if (n >= NN) return;
    float4 x0 = *(const float4*)&g_agg1[n * HH];
    float4 x1 = *(const float4*)&g_agg1[n * HH + 4];
    float xv[HH] = {fmaxf(x0.x,0.f), fmaxf(x0.y,0.f), fmaxf(x0.z,0.f), fmaxf(x0.w,0.f),
                    fmaxf(x1.x,0.f), fmaxf(x1.y,0.f), fmaxf(x1.z,0.f), fmaxf(x1.w,0.f)};
    float v[CC];
    float m = -INFINITY;
#pragma unroll
    for (int c = 0; c < CC; c++) {
        float s = g_agg2[n * CC + c] + sb[c];
#pragma unroll
        for (int h = 0; h < HH; h++) s += xv[h] * sr[h * CC + c];
        v[c] = s;
        m = fmaxf(m, s);
    }
    float sum = 0.0f;
#pragma unroll
    for (int c = 0; c < CC; c++) sum += __expf(v[c] - m);
    float lse = m + __logf(sum);
#pragma unroll
    for (int c = 0; c < CC; c++) out[n * CC + c] = v[c] - lse;
}

extern "C" void kernel_launch(void* const* d_in, const int* in_sizes, int n_in,
                              void* d_out, int out_size) {
    const int*   edge_index = (const int*)d_in[0];   // (2, E)
    const int*   edge_type  = (const int*)d_in[1];   // (E,)
    const float* basis1     = (const float*)d_in[2]; // (B, N, H)
    const float* comp1      = (const float*)d_in[3]; // (R, B)
    const float* root1      = (const float*)d_in[4]; // (N, H)
    const float* bias1      = (const float*)d_in[5]; // (H,)
    const float* basis2     = (const float*)d_in[6]; // (B, H, C)
    const float* comp2      = (const float*)d_in[7]; // (R, B)
    const float* root2      = (const float*)d_in[8]; // (H, C)
    const float* bias2      = (const float*)d_in[9]; // (C,)
    float* out = (float*)d_out;

    k_setup<<<2048, 256>>>(basis2, comp2, root1, bias1);               // idx 0
    k_cw1<<<(EE / 2 + 255) / 256, 256>>>(edge_index, edge_type,
                                         basis1, comp1);               // idx 1
    k_scatter1<<<(EE / 2 + 255) / 256, 256>>>(edge_index, edge_type);  // idx 2
    k_scatter2<<<(EE / 2 + 255) / 256, 256>>>(edge_index, edge_type);  // idx 3 (profiled)
    k_final<<<(NN + 127) / 128, 128>>>(root2, bias2, out);             // idx 4
}